// round 1
// baseline (speedup 1.0000x reference)
#include <cuda_runtime.h>
#include <math.h>

// Dims
#define BB 16
#define NCI 64
#define NCO 64
#define NHID 16
#define NT 16
#define NHW 1024

// ---------------- persistent scratch (device globals; no allocation) -------
__device__ float g_h  [BB*NCO*NHW];     // attended h (recurrent carry)   4 MB
__device__ float g_hg [BB*NCO*NHW];     // pre-attention h (gate output)  4 MB
__device__ float g_c  [BB*NCO*NHW];     // cell state                     4 MB
__device__ float g_conv[BB*4*NCO*NHW];  // conv output (B,256,32,32)     16 MB
__device__ float g_q  [BB*NHID*NHW];    //  1 MB
__device__ float g_k  [BB*NHID*NHW];    //  1 MB
__device__ float g_v  [BB*NCO*NHW];     //  4 MB
__device__ float g_P  [BB*NHW*NHW];     // attention probs               64 MB

// ---------------- init: zero h and c ---------------------------------------
__global__ void k_init()
{
    int i = blockIdx.x * 256 + threadIdx.x;   // 1,048,576 elements
    g_h[i] = 0.f;
    g_c[i] = 0.f;
}

// ---------------- conv: (B,128,32,32) -> (B,256,32,32), 3x3 SAME -----------
// grid (16 cout-groups, 16 batch), 256 threads.
// Block: batch b, cout [co0,co0+16), full 32x32 image.
// Thread: 4 adjacent x-positions, 16 cout -> 64 accumulators.
__global__ void __launch_bounds__(256, 2) k_conv(
    const float* __restrict__ X, const float* __restrict__ Wc,
    const float* __restrict__ bc, int t)
{
    __shared__ float in_s[4 * 34 * 37];   // 4 ci, 34 rows, stride 37 (20.1 KB)
    __shared__ float w_s[16 * 36];        // 16 co x 4 ci x 9           (2.3 KB)

    const int b   = blockIdx.y;
    const int co0 = blockIdx.x * 16;
    const int tid = threadIdx.x;
    const int y   = tid >> 3;            // 0..31
    const int x4  = (tid & 7) << 2;      // 0,4,...,28

    float acc[16][4];
    #pragma unroll
    for (int i = 0; i < 16; ++i)
        #pragma unroll
        for (int p = 0; p < 4; ++p) acc[i][p] = 0.f;

    for (int ch = 0; ch < 32; ++ch) {            // 32 chunks of 4 input ch.
        // stage weights
        for (int i = tid; i < 576; i += 256) {
            int co = i / 36; int r = i - co * 36;
            w_s[i] = Wc[((co0 + co) * 128 + (ch * 4 + r / 9)) * 9 + (r % 9)];
        }
        // stage input halo (34x34 per ci, zero-padded borders)
        for (int i = tid; i < 4 * 1156; i += 256) {
            int cc = i / 1156; int r = i - cc * 1156;
            int yy = r / 34;   int xx = r - yy * 34;
            int iy = yy - 1,   ix = xx - 1;
            int ci = ch * 4 + cc;
            const float* src = (ci < 64)
                ? (X + ((b * 64 + ci) * 16 + t) * 1024)
                : (g_h + (b * 64 + (ci - 64)) * 1024);
            float v = 0.f;
            if (iy >= 0 && iy < 32 && ix >= 0 && ix < 32) v = src[iy * 32 + ix];
            in_s[cc * 1258 + yy * 37 + xx] = v;
        }
        __syncthreads();

        #pragma unroll
        for (int cc = 0; cc < 4; ++cc) {
            float v[3][6];
            #pragma unroll
            for (int dy = 0; dy < 3; ++dy)
                #pragma unroll
                for (int dx = 0; dx < 6; ++dx)
                    v[dy][dx] = in_s[cc * 1258 + (y + dy) * 37 + (x4 + dx)];
            #pragma unroll
            for (int co = 0; co < 16; ++co) {
                const float* wp = &w_s[co * 36 + cc * 9];
                float w0 = wp[0], w1 = wp[1], w2 = wp[2];
                float w3 = wp[3], w4 = wp[4], w5 = wp[5];
                float w6 = wp[6], w7 = wp[7], w8 = wp[8];
                #pragma unroll
                for (int p = 0; p < 4; ++p) {
                    acc[co][p] += w0 * v[0][p] + w1 * v[0][p + 1] + w2 * v[0][p + 2]
                                + w3 * v[1][p] + w4 * v[1][p + 1] + w5 * v[1][p + 2]
                                + w6 * v[2][p] + w7 * v[2][p + 1] + w8 * v[2][p + 2];
                }
            }
        }
        __syncthreads();
    }

    #pragma unroll
    for (int co = 0; co < 16; ++co) {
        float bv = bc[co0 + co];
        #pragma unroll
        for (int p = 0; p < 4; ++p)
            g_conv[(b * 256 + co0 + co) * 1024 + y * 32 + x4 + p] = acc[co][p] + bv;
    }
}

// ---------------- ConvLSTM gating (elementwise, peephole) ------------------
__device__ __forceinline__ float sigf(float x) { return 1.f / (1.f + __expf(-x)); }

__global__ void k_gate(const float* __restrict__ Wci,
                       const float* __restrict__ Wcf,
                       const float* __restrict__ Wco)
{
    int idx = blockIdx.x * 256 + threadIdx.x;   // (b,c,pos) over 1M elements
    int b   = idx >> 16;
    int c   = (idx >> 10) & 63;
    int pos = idx & 1023;
    int cb  = (b * 256 + c) * 1024 + pos;

    float ic = g_conv[cb];
    float fc = g_conv[cb + 64 * 1024];
    float gc = g_conv[cb + 128 * 1024];
    float oc = g_conv[cb + 192 * 1024];
    float cp = g_c[idx];
    int   wp = c * 1024 + pos;

    float i  = sigf(ic + Wci[wp] * cp);
    float f  = sigf(fc + Wcf[wp] * cp);
    float nc = f * cp + i * tanhf(gc);
    float o  = sigf(oc + Wco[wp] * nc);
    g_c[idx]  = nc;
    g_hg[idx] = o * tanhf(nc);
}

// ---------------- q,k,v 1x1 convs: 96 output ch from 64 --------------------
// grid (4 pos-tiles, 12 oc-groups of 8, 16 batch), 256 threads (1 pos each).
__global__ void k_qkv(const float* __restrict__ qw, const float* __restrict__ qb,
                      const float* __restrict__ kw, const float* __restrict__ kb,
                      const float* __restrict__ vw, const float* __restrict__ vb)
{
    __shared__ float h_s[32 * 256];   // 32 KB, half the channels at a time
    __shared__ float w_s[8 * 64];     // 2 KB

    const int p0  = blockIdx.x * 256;
    const int oc0 = blockIdx.y * 8;
    const int b   = blockIdx.z;
    const int tid = threadIdx.x;

    for (int i = tid; i < 512; i += 256) {
        int j = i >> 6; int c = i & 63; int oc = oc0 + j;
        w_s[i] = (oc < 16) ? qw[oc * 64 + c]
               : (oc < 32) ? kw[(oc - 16) * 64 + c]
                           : vw[(oc - 32) * 64 + c];
    }

    float acc[8];
    #pragma unroll
    for (int j = 0; j < 8; ++j) {
        int oc = oc0 + j;
        acc[j] = (oc < 16) ? qb[oc] : (oc < 32) ? kb[oc - 16] : vb[oc - 32];
    }

    for (int ch = 0; ch < 2; ++ch) {
        __syncthreads();
        for (int i = tid; i < 8192; i += 256) {
            int c = i >> 8; int j = i & 255;
            h_s[i] = g_hg[(b * 64 + ch * 32 + c) * 1024 + p0 + j];
        }
        __syncthreads();
        #pragma unroll 8
        for (int c = 0; c < 32; ++c) {
            float hv = h_s[c * 256 + tid];
            #pragma unroll
            for (int j = 0; j < 8; ++j)
                acc[j] += w_s[j * 64 + ch * 32 + c] * hv;
        }
    }

    int pos = p0 + tid;
    #pragma unroll
    for (int j = 0; j < 8; ++j) {
        int oc = oc0 + j;
        if (oc < 16)      g_q[(b * 16 + oc) * 1024 + pos]        = acc[j];
        else if (oc < 32) g_k[(b * 16 + (oc - 16)) * 1024 + pos] = acc[j];
        else              g_v[(b * 64 + (oc - 32)) * 1024 + pos] = acc[j];
    }
}

// ---------------- scores + softmax fused: P[b][n][m] ------------------------
// grid (64 row-groups, 16 batch), 256 threads. Warp = 2 rows, scores in regs.
__global__ void __launch_bounds__(256, 2) k_scores()
{
    __shared__ float k_s[16 * 512];   // 32 KB, half of k's m-range at a time
    const int b    = blockIdx.y;
    const int r0   = blockIdx.x * 16 + ((threadIdx.x >> 5) << 1);
    const int lane = threadIdx.x & 31;

    float q0[16], q1[16];
    #pragma unroll
    for (int c = 0; c < 16; ++c) {
        q0[c] = g_q[(b * 16 + c) * 1024 + r0];
        q1[c] = g_q[(b * 16 + c) * 1024 + r0 + 1];
    }

    float s0[32], s1[32];
    for (int ch = 0; ch < 2; ++ch) {
        __syncthreads();
        for (int i = threadIdx.x; i < 8192; i += 256) {
            int c = i >> 9; int mm = i & 511;
            k_s[i] = g_k[(b * 16 + c) * 1024 + ch * 512 + mm];
        }
        __syncthreads();
        #pragma unroll
        for (int jj = 0; jj < 16; ++jj) {
            int j  = ch * 16 + jj;
            int mm = jj * 32 + lane;
            float a = 0.f, bb2 = 0.f;
            #pragma unroll
            for (int c = 0; c < 16; ++c) {
                float kv = k_s[c * 512 + mm];
                a   += q0[c] * kv;
                bb2 += q1[c] * kv;
            }
            s0[j] = a; s1[j] = bb2;
        }
    }

    float m0 = -1e30f, m1 = -1e30f;
    #pragma unroll
    for (int j = 0; j < 32; ++j) { m0 = fmaxf(m0, s0[j]); m1 = fmaxf(m1, s1[j]); }
    #pragma unroll
    for (int o = 16; o > 0; o >>= 1) {
        m0 = fmaxf(m0, __shfl_xor_sync(0xffffffffu, m0, o));
        m1 = fmaxf(m1, __shfl_xor_sync(0xffffffffu, m1, o));
    }
    float sum0 = 0.f, sum1 = 0.f;
    #pragma unroll
    for (int j = 0; j < 32; ++j) {
        s0[j] = __expf(s0[j] - m0); sum0 += s0[j];
        s1[j] = __expf(s1[j] - m1); sum1 += s1[j];
    }
    #pragma unroll
    for (int o = 16; o > 0; o >>= 1) {
        sum0 += __shfl_xor_sync(0xffffffffu, sum0, o);
        sum1 += __shfl_xor_sync(0xffffffffu, sum1, o);
    }
    float inv0 = 1.f / sum0, inv1 = 1.f / sum1;

    float* P0 = g_P + b * 1048576 + r0 * 1024;
    #pragma unroll
    for (int j = 0; j < 32; ++j) {
        P0[j * 32 + lane]        = s0[j] * inv0;
        P0[1024 + j * 32 + lane] = s1[j] * inv1;
    }
}

// ---------------- z = P @ v^T, fused with z_w 1x1 + output write -----------
// grid (8 n-tiles of 128, 16 batch), 256 threads. Warp = 8 channels,
// lane = 4 n-columns (l, l+32, l+64, l+96).
__global__ void __launch_bounds__(256) k_zout(
    const float* __restrict__ zw, const float* __restrict__ zb,
    float* __restrict__ out, int t)
{
    __shared__ float smem[12288];          // 48 KB, phase-unioned
    float* P_s  = smem;                    // phase 1: 128 x 33   (16896 B)
    float* v_s  = smem + 4224;             // phase 1: 64 x 32    ( 8192 B)
    float* z_s  = smem;                    // phase 2: 64 x 128   (32768 B)
    float* zw_s = smem + 8192;             // phase 2: 64 x 64    (16384 B)

    const int b   = blockIdx.y;
    const int n0  = blockIdx.x * 128;
    const int tid = threadIdx.x;
    const int w   = tid >> 5;
    const int l   = tid & 31;

    float acc[8][4];
    #pragma unroll
    for (int ci = 0; ci < 8; ++ci)
        #pragma unroll
        for (int i = 0; i < 4; ++i) acc[ci][i] = 0.f;

    for (int m0 = 0; m0 < 1024; m0 += 32) {
        for (int i = tid; i < 4096; i += 256) {
            int nl = i >> 5; int kk = i & 31;
            P_s[nl * 33 + kk] = g_P[b * 1048576 + (n0 + nl) * 1024 + m0 + kk];
        }
        for (int i = tid; i < 2048; i += 256) {
            int c = i >> 5; int kk = i & 31;
            v_s[i] = g_v[(b * 64 + c) * 1024 + m0 + kk];
        }
        __syncthreads();
        #pragma unroll 4
        for (int kk = 0; kk < 32; ++kk) {
            float pv[4];
            #pragma unroll
            for (int i = 0; i < 4; ++i) pv[i] = P_s[(l + 32 * i) * 33 + kk];
            #pragma unroll
            for (int ci = 0; ci < 8; ++ci) {
                float vv = v_s[(w * 8 + ci) * 32 + kk];
                #pragma unroll
                for (int i = 0; i < 4; ++i) acc[ci][i] += vv * pv[i];
            }
        }
        __syncthreads();
    }

    // stash z tile, stage z_w
    #pragma unroll
    for (int ci = 0; ci < 8; ++ci)
        #pragma unroll
        for (int i = 0; i < 4; ++i)
            z_s[(w * 8 + ci) * 128 + l + 32 * i] = acc[ci][i];
    for (int i = tid; i < 4096; i += 256) zw_s[i] = zw[i];
    __syncthreads();

    // attended = z_w @ z + z_b
    float acc2[8][4];
    #pragma unroll
    for (int ci = 0; ci < 8; ++ci) {
        float bv = zb[w * 8 + ci];
        #pragma unroll
        for (int i = 0; i < 4; ++i) acc2[ci][i] = bv;
    }
    #pragma unroll 8
    for (int c = 0; c < 64; ++c) {
        float pv[4];
        #pragma unroll
        for (int i = 0; i < 4; ++i) pv[i] = z_s[c * 128 + l + 32 * i];
        #pragma unroll
        for (int ci = 0; ci < 8; ++ci) {
            float wv = zw_s[(w * 8 + ci) * 64 + c];
            #pragma unroll
            for (int i = 0; i < 4; ++i) acc2[ci][i] += wv * pv[i];
        }
    }

    #pragma unroll
    for (int ci = 0; ci < 8; ++ci) {
        int oc = w * 8 + ci;
        #pragma unroll
        for (int i = 0; i < 4; ++i) {
            int n = n0 + l + 32 * i;
            float val = acc2[ci][i];
            g_h[(b * 64 + oc) * 1024 + n] = val;                  // recurrent carry
            out[((b * 64 + oc) * 16 + t) * 1024 + n] = val;       // (B,C,T,H,W)
        }
    }
}

// ---------------- orchestration --------------------------------------------
extern "C" void kernel_launch(void* const* d_in, const int* in_sizes, int n_in,
                              void* d_out, int out_size)
{
    (void)in_sizes; (void)n_in; (void)out_size;
    const float* X   = (const float*)d_in[0];
    const float* Wc  = (const float*)d_in[1];
    const float* bc  = (const float*)d_in[2];
    const float* Wci = (const float*)d_in[3];
    const float* Wcf = (const float*)d_in[4];
    const float* Wco = (const float*)d_in[5];
    const float* qw  = (const float*)d_in[6];
    const float* qb  = (const float*)d_in[7];
    const float* kw  = (const float*)d_in[8];
    const float* kb  = (const float*)d_in[9];
    const float* vw  = (const float*)d_in[10];
    const float* vb  = (const float*)d_in[11];
    const float* zw  = (const float*)d_in[12];
    const float* zb  = (const float*)d_in[13];
    float* out = (float*)d_out;

    k_init<<<4096, 256>>>();
    for (int t = 0; t < NT; ++t) {
        k_conv  <<<dim3(16, 16),    256>>>(X, Wc, bc, t);
        k_gate  <<<4096,            256>>>(Wci, Wcf, Wco);
        k_qkv   <<<dim3(4, 12, 16), 256>>>(qw, qb, kw, kb, vw, vb);
        k_scores<<<dim3(64, 16),    256>>>();
        k_zout  <<<dim3(8, 16),     256>>>(zw, zb, out, t);
    }
}